// round 1
// baseline (speedup 1.0000x reference)
#include <cuda_runtime.h>
#include <stdint.h>

// Problem constants (fixed by setup_inputs)
#define NPOI   50000
#define DIM    256
#define NELEM  (NPOI * DIM)      // 12,800,000 floats per dense operand
#define NV4    (NELEM / 4)       // 3,200,000 float4
#define THRESH 0xE6666600u       // bits < THRESH  <=>  uniform(bits) < 0.9f
#define KEEP_INV (1.0f / 0.9f)

// ---------------- scratch (static device globals; no runtime allocs) --------
__device__ float4 g_x[NV4];      // current layer activation x_i
__device__ float4 g_mt[NV4];     // msg_tar  [H, D]
__device__ float4 g_ms[NV4];     // msg_src  [N, D]
__device__ float4 g_acc[NV4];    // running sum of finals

// ---------------- COO scatter SpMM: Y[rows[e]] += vals[e] * X[cols[e]] ------
// one warp per edge; 2 float4 per lane covers D=256; vector red -> 16B atomics
__global__ void __launch_bounds__(256) spmm_kernel(
    const int* __restrict__ rows, const int* __restrict__ cols,
    const float* __restrict__ vals, const float4* __restrict__ X,
    float4* __restrict__ Y, int nnz)
{
    int e    = (int)((blockIdx.x * 256u + threadIdx.x) >> 5);
    int lane = threadIdx.x & 31;
    if (e >= nnz) return;
    int   r = __ldg(rows + e);
    int   c = __ldg(cols + e);
    float v = __ldg(vals + e);

    const float4* xr = X + (size_t)c * (DIM / 4);
    float4*       yr = Y + (size_t)r * (DIM / 4);

    float4 a0 = __ldg(xr + lane);
    float4 a1 = __ldg(xr + lane + 32);

    asm volatile("red.global.add.v4.f32 [%0], {%1, %2, %3, %4};"
        :: "l"(yr + lane),
           "f"(v * a0.x), "f"(v * a0.y), "f"(v * a0.z), "f"(v * a0.w)
        : "memory");
    asm volatile("red.global.add.v4.f32 [%0], {%1, %2, %3, %4};"
        :: "l"(yr + lane + 32),
           "f"(v * a1.x), "f"(v * a1.y), "f"(v * a1.z), "f"(v * a1.w)
        : "memory");
}

// ---------------- Threefry-2x32 (JAX), partitionable random_bits ------------
// counter = 64-bit iota -> (hi=0, lo=idx); 32-bit output = o0 ^ o1
__device__ __forceinline__ uint32_t tf_bits(uint32_t k0, uint32_t k1,
                                            uint32_t k2, uint32_t ctr)
{
    uint32_t x0 = k0;           // 0 + ks[0]
    uint32_t x1 = ctr + k1;     // ctr + ks[1]
#define TFR(r) { x0 += x1; x1 = __funnelshift_l(x1, x1, (r)); x1 ^= x0; }
    TFR(13) TFR(15) TFR(26) TFR(6)    x0 += k1; x1 += k2 + 1u;
    TFR(17) TFR(29) TFR(16) TFR(24)   x0 += k2; x1 += k0 + 2u;
    TFR(13) TFR(15) TFR(26) TFR(6)    x0 += k0; x1 += k1 + 3u;
    TFR(17) TFR(29) TFR(16) TFR(24)   x0 += k1; x1 += k2 + 4u;
    TFR(13) TFR(15) TFR(26) TFR(6)    x0 += k2; x1 += k0 + 5u;
#undef TFR
    return x0 ^ x1;
}

// ---------------- fused residual + dropout + accumulate (+final mean) -------
// mode 0: x = drop(msg+poi); acc = poi + x          (xprev == poi_embs)
// mode 1: x = drop(msg+x);   acc += x
// mode 2: v = drop(msg+x);   out = (acc + v) * 0.25
__global__ void __launch_bounds__(256) post_kernel(
    const float4* __restrict__ msg, const float4* __restrict__ xprev,
    float4* __restrict__ xout, float4* __restrict__ acc,
    float4* __restrict__ out, uint32_t k0, uint32_t k1, int mode)
{
    int t = blockIdx.x * 256 + threadIdx.x;
    if (t >= NV4) return;
    uint32_t base = (uint32_t)t * 4u;
    uint32_t k2 = k0 ^ k1 ^ 0x1BD11BDAu;

    uint32_t b0 = tf_bits(k0, k1, k2, base + 0u);
    uint32_t b1 = tf_bits(k0, k1, k2, base + 1u);
    uint32_t b2 = tf_bits(k0, k1, k2, base + 2u);
    uint32_t b3 = tf_bits(k0, k1, k2, base + 3u);

    float4 m = msg[t];
    float4 p = xprev[t];
    float4 v;
    v.x = (b0 < THRESH) ? (m.x + p.x) * KEEP_INV : 0.0f;
    v.y = (b1 < THRESH) ? (m.y + p.y) * KEEP_INV : 0.0f;
    v.z = (b2 < THRESH) ? (m.z + p.z) * KEEP_INV : 0.0f;
    v.w = (b3 < THRESH) ? (m.w + p.w) * KEEP_INV : 0.0f;

    if (mode == 0) {
        xout[t] = v;
        float4 a; a.x = p.x + v.x; a.y = p.y + v.y; a.z = p.z + v.z; a.w = p.w + v.w;
        acc[t] = a;
    } else if (mode == 1) {
        xout[t] = v;
        float4 a = acc[t];
        a.x += v.x; a.y += v.y; a.z += v.z; a.w += v.w;
        acc[t] = a;
    } else {
        float4 a = acc[t];
        float4 o;
        o.x = (a.x + v.x) * 0.25f; o.y = (a.y + v.y) * 0.25f;
        o.z = (a.z + v.z) * 0.25f; o.w = (a.w + v.w) * 0.25f;
        out[t] = o;
    }
}

// ---------------- host-side threefry (per-layer fold_in keys) ---------------
static inline unsigned h_rotl(unsigned x, int r) { return (x << r) | (x >> (32 - r)); }
static void host_threefry(unsigned k0, unsigned k1, unsigned x0, unsigned x1,
                          unsigned* o0, unsigned* o1)
{
    const int rots[2][4] = {{13, 15, 26, 6}, {17, 29, 16, 24}};
    unsigned ks[3] = {k0, k1, k0 ^ k1 ^ 0x1BD11BDAu};
    x0 += ks[0]; x1 += ks[1];
    for (int g = 0; g < 5; g++) {
        for (int j = 0; j < 4; j++) {
            x0 += x1; x1 = h_rotl(x1, rots[g & 1][j]); x1 ^= x0;
        }
        x0 += ks[(g + 1) % 3];
        x1 += ks[(g + 2) % 3] + (unsigned)(g + 1);
    }
    *o0 = x0; *o1 = x1;
}

extern "C" void kernel_launch(void* const* d_in, const int* in_sizes, int n_in,
                              void* d_out, int out_size)
{
    const float* poi     = (const float*)d_in[0];
    const int*   src_row = (const int*)  d_in[1];
    const int*   src_col = (const int*)  d_in[2];
    const float* src_val = (const float*)d_in[3];
    const int*   tar_row = (const int*)  d_in[4];
    const int*   tar_col = (const int*)  d_in[5];
    const float* tar_val = (const float*)d_in[6];
    int nnz = in_sizes[1];

    float4 *x, *mt, *ms, *acc;
    cudaGetSymbolAddress((void**)&x,   g_x);
    cudaGetSymbolAddress((void**)&mt,  g_mt);
    cudaGetSymbolAddress((void**)&ms,  g_ms);
    cudaGetSymbolAddress((void**)&acc, g_acc);

    // per-layer dropout keys: fold_in(key(42), i) = threefry((0,42), (0,i))
    unsigned lk0[3], lk1[3];
    for (unsigned i = 0; i < 3; i++)
        host_threefry(0u, 42u, 0u, i, &lk0[i], &lk1[i]);

    int spmm_blocks = (nnz + 7) / 8;          // 8 edges (warps) per 256-thr block
    int post_blocks = (NV4 + 255) / 256;      // 12500

    const float4* xin = (const float4*)poi;   // layer 0 reads poi_embs directly
    for (int i = 0; i < 3; i++) {
        // msg_tar = spmm(tar_row, tar_col, tar_val, x)   [H, D]
        cudaMemsetAsync(mt, 0, (size_t)NELEM * sizeof(float), 0);
        spmm_kernel<<<spmm_blocks, 256>>>(tar_row, tar_col, tar_val, xin, mt, nnz);
        // msg_src = spmm(src_row, src_col, src_val, msg_tar)   [N, D]
        cudaMemsetAsync(ms, 0, (size_t)NELEM * sizeof(float), 0);
        spmm_kernel<<<spmm_blocks, 256>>>(src_row, src_col, src_val, mt, ms, nnz);
        // x = dropout(msg_src + x_prev); acc bookkeeping; final layer -> mean
        post_kernel<<<post_blocks, 256>>>(ms, xin, x, acc, (float4*)d_out,
                                          lk0[i], lk1[i], i);
        xin = (const float4*)x;
    }
}

// round 2
// speedup vs baseline: 2.5389x; 2.5389x over previous
#include <cuda_runtime.h>
#include <stdint.h>

// Problem constants (fixed by setup_inputs)
#define NPOI    50000
#define DIM     256
#define D4      (DIM / 4)            // 64 float4 per row
#define NELEM   (NPOI * DIM)
#define NV4     (NELEM / 4)
#define NNZ_MAX 1600000
#define THRESH  0xE6666600u          // bits < THRESH <=> uniform(bits) < 0.9f
#define KEEP_INV (1.0f / 0.9f)

// ---------------- scratch (static device globals) ---------------------------
__device__ float4 g_x[NV4];          // layer activation x_i
__device__ float4 g_mt[NV4];         // msg_tar [H, D]
__device__ float4 g_acc[NV4];        // running sum of finals
__device__ int    g_rp_src[NPOI + 1], g_rp_tar[NPOI + 1];
__device__ int    g_cur_src[NPOI],   g_cur_tar[NPOI];
__device__ int    g_cnt[NPOI];
__device__ int    g_ccol_src[NNZ_MAX], g_ccol_tar[NNZ_MAX];
__device__ float  g_cval_src[NNZ_MAX], g_cval_tar[NNZ_MAX];

// ---------------- CSR build: histogram --------------------------------------
__global__ void __launch_bounds__(256) hist_kernel(
    const int* __restrict__ rows, int* __restrict__ cnt, int nnz)
{
    int e = blockIdx.x * 256 + threadIdx.x;
    if (e < nnz) atomicAdd(cnt + __ldg(rows + e), 1);
}

// ---------------- CSR build: single-block exclusive scan --------------------
__global__ void __launch_bounds__(1024) scan_kernel(
    const int* __restrict__ cnt, int* __restrict__ rowptr,
    int* __restrict__ cursor, int n)
{
    __shared__ int carry;
    __shared__ int wsum[32];
    int tid = threadIdx.x, lane = tid & 31, wid = tid >> 5;
    if (tid == 0) carry = 0;
    __syncthreads();
    for (int base = 0; base < n; base += 1024) {
        int c0 = carry;
        int i = base + tid;
        int v = (i < n) ? cnt[i] : 0;
        int inc = v;
        #pragma unroll
        for (int o = 1; o < 32; o <<= 1) {
            int t = __shfl_up_sync(0xFFFFFFFFu, inc, o);
            if (lane >= o) inc += t;
        }
        if (lane == 31) wsum[wid] = inc;
        __syncthreads();
        if (wid == 0) {
            int s = wsum[lane];
            #pragma unroll
            for (int o = 1; o < 32; o <<= 1) {
                int t = __shfl_up_sync(0xFFFFFFFFu, s, o);
                if (lane >= o) s += t;
            }
            wsum[lane] = s;
        }
        __syncthreads();
        int block_incl = inc + (wid ? wsum[wid - 1] : 0);
        if (i < n) { int ex = c0 + block_incl - v; rowptr[i] = ex; cursor[i] = ex; }
        __syncthreads();
        if (tid == 1023) carry = c0 + block_incl;
        __syncthreads();
    }
    if (tid == 0) rowptr[n] = carry;
}

// ---------------- CSR build: scatter-permute cols/vals ----------------------
__global__ void __launch_bounds__(256) scatter_kernel(
    const int* __restrict__ rows, const int* __restrict__ cols,
    const float* __restrict__ vals, int* __restrict__ cursor,
    int* __restrict__ ccol, float* __restrict__ cval, int nnz)
{
    int e = blockIdx.x * 256 + threadIdx.x;
    if (e >= nnz) return;
    int pos = atomicAdd(cursor + __ldg(rows + e), 1);
    ccol[pos] = __ldg(cols + e);
    cval[pos] = __ldg(vals + e);
}

// ---------------- gather SpMM (CSR): Y[r] = sum v * X[c] --------------------
// 256-thread block = 4 groups of 64; each group owns one row, thread owns one f4
__global__ void __launch_bounds__(256) spmm_csr(
    const int* __restrict__ rowptr, const int* __restrict__ cols,
    const float* __restrict__ vals, const float4* __restrict__ X,
    float4* __restrict__ Y)
{
    int row = blockIdx.x * 4 + (threadIdx.x >> 6);
    int g   = threadIdx.x & 63;
    int s = __ldg(rowptr + row), e = __ldg(rowptr + row + 1);
    float4 acc = make_float4(0.f, 0.f, 0.f, 0.f);
    int j = s;
    for (; j + 1 < e; j += 2) {
        int   c0 = __ldg(cols + j),     c1 = __ldg(cols + j + 1);
        float v0 = __ldg(vals + j),     v1 = __ldg(vals + j + 1);
        float4 a0 = __ldg(X + (size_t)c0 * D4 + g);
        float4 a1 = __ldg(X + (size_t)c1 * D4 + g);
        acc.x = fmaf(v0, a0.x, acc.x); acc.y = fmaf(v0, a0.y, acc.y);
        acc.z = fmaf(v0, a0.z, acc.z); acc.w = fmaf(v0, a0.w, acc.w);
        acc.x = fmaf(v1, a1.x, acc.x); acc.y = fmaf(v1, a1.y, acc.y);
        acc.z = fmaf(v1, a1.z, acc.z); acc.w = fmaf(v1, a1.w, acc.w);
    }
    if (j < e) {
        int c0 = __ldg(cols + j); float v0 = __ldg(vals + j);
        float4 a0 = __ldg(X + (size_t)c0 * D4 + g);
        acc.x = fmaf(v0, a0.x, acc.x); acc.y = fmaf(v0, a0.y, acc.y);
        acc.z = fmaf(v0, a0.z, acc.z); acc.w = fmaf(v0, a0.w, acc.w);
    }
    Y[(size_t)row * D4 + g] = acc;
}

// ---------------- Threefry-2x32 (JAX partitionable random_bits) -------------
__device__ __forceinline__ uint32_t tf_bits(uint32_t k0, uint32_t k1,
                                            uint32_t k2, uint32_t ctr)
{
    uint32_t x0 = k0;
    uint32_t x1 = ctr + k1;
#define TFR(r) { x0 += x1; x1 = __funnelshift_l(x1, x1, (r)); x1 ^= x0; }
    TFR(13) TFR(15) TFR(26) TFR(6)    x0 += k1; x1 += k2 + 1u;
    TFR(17) TFR(29) TFR(16) TFR(24)   x0 += k2; x1 += k0 + 2u;
    TFR(13) TFR(15) TFR(26) TFR(6)    x0 += k0; x1 += k1 + 3u;
    TFR(17) TFR(29) TFR(16) TFR(24)   x0 += k1; x1 += k2 + 4u;
    TFR(13) TFR(15) TFR(26) TFR(6)    x0 += k2; x1 += k0 + 5u;
#undef TFR
    return x0 ^ x1;
}

// ------- gather SpMM fused with residual + dropout + accumulate + mean ------
// mode 0: x = drop(msg+poi); acc = poi + x
// mode 1: x = drop(msg+x);   acc += x
// mode 2: v = drop(msg+x);   out = (acc + v) * 0.25
__global__ void __launch_bounds__(256) spmm_csr_fused(
    const int* __restrict__ rowptr, const int* __restrict__ cols,
    const float* __restrict__ vals, const float4* __restrict__ X,
    const float4* __restrict__ xprev, float4* __restrict__ xout,
    float4* __restrict__ accbuf, float4* __restrict__ out,
    uint32_t k0, uint32_t k1, int mode)
{
    int row = blockIdx.x * 4 + (threadIdx.x >> 6);
    int g   = threadIdx.x & 63;
    int s = __ldg(rowptr + row), e = __ldg(rowptr + row + 1);
    float4 m = make_float4(0.f, 0.f, 0.f, 0.f);
    int j = s;
    for (; j + 1 < e; j += 2) {
        int   c0 = __ldg(cols + j),     c1 = __ldg(cols + j + 1);
        float v0 = __ldg(vals + j),     v1 = __ldg(vals + j + 1);
        float4 a0 = __ldg(X + (size_t)c0 * D4 + g);
        float4 a1 = __ldg(X + (size_t)c1 * D4 + g);
        m.x = fmaf(v0, a0.x, m.x); m.y = fmaf(v0, a0.y, m.y);
        m.z = fmaf(v0, a0.z, m.z); m.w = fmaf(v0, a0.w, m.w);
        m.x = fmaf(v1, a1.x, m.x); m.y = fmaf(v1, a1.y, m.y);
        m.z = fmaf(v1, a1.z, m.z); m.w = fmaf(v1, a1.w, m.w);
    }
    if (j < e) {
        int c0 = __ldg(cols + j); float v0 = __ldg(vals + j);
        float4 a0 = __ldg(X + (size_t)c0 * D4 + g);
        m.x = fmaf(v0, a0.x, m.x); m.y = fmaf(v0, a0.y, m.y);
        m.z = fmaf(v0, a0.z, m.z); m.w = fmaf(v0, a0.w, m.w);
    }

    size_t idx4 = (size_t)row * D4 + g;
    uint32_t base = (uint32_t)idx4 * 4u;
    uint32_t k2 = k0 ^ k1 ^ 0x1BD11BDAu;
    uint32_t b0 = tf_bits(k0, k1, k2, base + 0u);
    uint32_t b1 = tf_bits(k0, k1, k2, base + 1u);
    uint32_t b2 = tf_bits(k0, k1, k2, base + 2u);
    uint32_t b3 = tf_bits(k0, k1, k2, base + 3u);

    float4 p = xprev[idx4];
    float4 v;
    v.x = (b0 < THRESH) ? (m.x + p.x) * KEEP_INV : 0.0f;
    v.y = (b1 < THRESH) ? (m.y + p.y) * KEEP_INV : 0.0f;
    v.z = (b2 < THRESH) ? (m.z + p.z) * KEEP_INV : 0.0f;
    v.w = (b3 < THRESH) ? (m.w + p.w) * KEEP_INV : 0.0f;

    if (mode == 0) {
        xout[idx4] = v;
        accbuf[idx4] = make_float4(p.x + v.x, p.y + v.y, p.z + v.z, p.w + v.w);
    } else if (mode == 1) {
        xout[idx4] = v;
        float4 a = accbuf[idx4];
        accbuf[idx4] = make_float4(a.x + v.x, a.y + v.y, a.z + v.z, a.w + v.w);
    } else {
        float4 a = accbuf[idx4];
        out[idx4] = make_float4((a.x + v.x) * 0.25f, (a.y + v.y) * 0.25f,
                                (a.z + v.z) * 0.25f, (a.w + v.w) * 0.25f);
    }
}

// ---------------- host-side threefry (per-layer fold_in keys) ---------------
static inline unsigned h_rotl(unsigned x, int r) { return (x << r) | (x >> (32 - r)); }
static void host_threefry(unsigned k0, unsigned k1, unsigned x0, unsigned x1,
                          unsigned* o0, unsigned* o1)
{
    const int rots[2][4] = {{13, 15, 26, 6}, {17, 29, 16, 24}};
    unsigned ks[3] = {k0, k1, k0 ^ k1 ^ 0x1BD11BDAu};
    x0 += ks[0]; x1 += ks[1];
    for (int g = 0; g < 5; g++) {
        for (int j = 0; j < 4; j++) {
            x0 += x1; x1 = h_rotl(x1, rots[g & 1][j]); x1 ^= x0;
        }
        x0 += ks[(g + 1) % 3];
        x1 += ks[(g + 2) % 3] + (unsigned)(g + 1);
    }
    *o0 = x0; *o1 = x1;
}

extern "C" void kernel_launch(void* const* d_in, const int* in_sizes, int n_in,
                              void* d_out, int out_size)
{
    const float* poi     = (const float*)d_in[0];
    const int*   src_row = (const int*)  d_in[1];
    const int*   src_col = (const int*)  d_in[2];
    const float* src_val = (const float*)d_in[3];
    const int*   tar_row = (const int*)  d_in[4];
    const int*   tar_col = (const int*)  d_in[5];
    const float* tar_val = (const float*)d_in[6];
    int nnz = in_sizes[1];

    float4 *x, *mt, *acc;
    int *rp_s, *rp_t, *cur_s, *cur_t, *cnt, *ccol_s, *ccol_t;
    float *cval_s, *cval_t;
    cudaGetSymbolAddress((void**)&x,      g_x);
    cudaGetSymbolAddress((void**)&mt,     g_mt);
    cudaGetSymbolAddress((void**)&acc,    g_acc);
    cudaGetSymbolAddress((void**)&rp_s,   g_rp_src);
    cudaGetSymbolAddress((void**)&rp_t,   g_rp_tar);
    cudaGetSymbolAddress((void**)&cur_s,  g_cur_src);
    cudaGetSymbolAddress((void**)&cur_t,  g_cur_tar);
    cudaGetSymbolAddress((void**)&cnt,    g_cnt);
    cudaGetSymbolAddress((void**)&ccol_s, g_ccol_src);
    cudaGetSymbolAddress((void**)&ccol_t, g_ccol_tar);
    cudaGetSymbolAddress((void**)&cval_s, g_cval_src);
    cudaGetSymbolAddress((void**)&cval_t, g_cval_tar);

    unsigned lk0[3], lk1[3];
    for (unsigned i = 0; i < 3; i++)
        host_threefry(0u, 42u, 0u, i, &lk0[i], &lk1[i]);

    int eb = (nnz + 255) / 256;
    int rb = NPOI / 4;               // 12500 blocks, 4 rows each

    // ---- CSR build for tar (rows over H) and src (rows over N) ----
    cudaMemsetAsync(cnt, 0, NPOI * sizeof(int), 0);
    hist_kernel<<<eb, 256>>>(tar_row, cnt, nnz);
    scan_kernel<<<1, 1024>>>(cnt, rp_t, cur_t, NPOI);
    scatter_kernel<<<eb, 256>>>(tar_row, tar_col, tar_val, cur_t, ccol_t, cval_t, nnz);

    cudaMemsetAsync(cnt, 0, NPOI * sizeof(int), 0);
    hist_kernel<<<eb, 256>>>(src_row, cnt, nnz);
    scan_kernel<<<1, 1024>>>(cnt, rp_s, cur_s, NPOI);
    scatter_kernel<<<eb, 256>>>(src_row, src_col, src_val, cur_s, ccol_s, cval_s, nnz);

    // ---- 3 layers ----
    const float4* xin = (const float4*)poi;
    for (int i = 0; i < 3; i++) {
        spmm_csr<<<rb, 256>>>(rp_t, ccol_t, cval_t, xin, mt);
        spmm_csr_fused<<<rb, 256>>>(rp_s, ccol_s, cval_s, mt, xin,
                                    x, acc, (float4*)d_out, lk0[i], lk1[i], i);
        xin = (const float4*)x;
    }
}

// round 3
// speedup vs baseline: 2.6652x; 1.0497x over previous
#include <cuda_runtime.h>
#include <stdint.h>

// Problem constants (fixed by setup_inputs)
#define NPOI    50000
#define DIM     256
#define D4      (DIM / 4)            // 64 float4 per row
#define NELEM   (NPOI * DIM)
#define NV4     (NELEM / 4)
#define NNZ_MAX 1600000
#define THRESH  0xE6666600u          // bits < THRESH <=> uniform(bits) < 0.9f
#define KEEP_INV (1.0f / 0.9f)

// ---------------- scratch (static device globals) ---------------------------
__device__ float4 g_x[NV4];          // layer activation x_i
__device__ float4 g_mt[NV4];         // msg_tar [H, D]
__device__ float4 g_acc[NV4];        // running sum of finals
__device__ int    g_rp_src[NPOI + 1], g_rp_tar[NPOI + 1];
__device__ int    g_cur_src[NPOI],   g_cur_tar[NPOI];
__device__ int    g_cnt[2 * NPOI];   // [0,N): tar counts, [N,2N): src counts
__device__ int2   g_e_src[NNZ_MAX];  // packed (col, val-bits)
__device__ int2   g_e_tar[NNZ_MAX];

// ---------------- CSR build: fused histogram (both matrices) ----------------
__global__ void __launch_bounds__(256) hist2_kernel(
    const int* __restrict__ tar_rows, const int* __restrict__ src_rows,
    int* __restrict__ cnt, int nnz)
{
    int e = blockIdx.x * 256 + threadIdx.x;
    if (e >= nnz) return;
    atomicAdd(cnt + __ldg(tar_rows + e), 1);
    atomicAdd(cnt + NPOI + __ldg(src_rows + e), 1);
}

// ---------------- CSR build: 2-block exclusive scan (block per matrix) ------
__global__ void __launch_bounds__(1024) scan2_kernel(
    const int* __restrict__ cnt,
    int* __restrict__ rp_t, int* __restrict__ cur_t,
    int* __restrict__ rp_s, int* __restrict__ cur_s)
{
    const int* c  = (blockIdx.x == 0) ? cnt  : cnt + NPOI;
    int* rowptr   = (blockIdx.x == 0) ? rp_t : rp_s;
    int* cursor   = (blockIdx.x == 0) ? cur_t : cur_s;
    const int n = NPOI;

    __shared__ int carry;
    __shared__ int wsum[32];
    int tid = threadIdx.x, lane = tid & 31, wid = tid >> 5;
    if (tid == 0) carry = 0;
    __syncthreads();
    for (int base = 0; base < n; base += 1024) {
        int c0 = carry;
        int i = base + tid;
        int v = (i < n) ? c[i] : 0;
        int inc = v;
        #pragma unroll
        for (int o = 1; o < 32; o <<= 1) {
            int t = __shfl_up_sync(0xFFFFFFFFu, inc, o);
            if (lane >= o) inc += t;
        }
        if (lane == 31) wsum[wid] = inc;
        __syncthreads();
        if (wid == 0) {
            int s = wsum[lane];
            #pragma unroll
            for (int o = 1; o < 32; o <<= 1) {
                int t = __shfl_up_sync(0xFFFFFFFFu, s, o);
                if (lane >= o) s += t;
            }
            wsum[lane] = s;
        }
        __syncthreads();
        int block_incl = inc + (wid ? wsum[wid - 1] : 0);
        if (i < n) { int ex = c0 + block_incl - v; rowptr[i] = ex; cursor[i] = ex; }
        __syncthreads();
        if (tid == 1023) carry = c0 + block_incl;
        __syncthreads();
    }
    if (tid == 0) rowptr[n] = carry;
}

// ---------------- CSR build: fused scatter-permute (packed int2) ------------
__global__ void __launch_bounds__(256) scatter2_kernel(
    const int* __restrict__ tar_rows, const int* __restrict__ tar_cols,
    const float* __restrict__ tar_vals,
    const int* __restrict__ src_rows, const int* __restrict__ src_cols,
    const float* __restrict__ src_vals,
    int* __restrict__ cur_t, int* __restrict__ cur_s,
    int2* __restrict__ et, int2* __restrict__ es, int nnz)
{
    int e = blockIdx.x * 256 + threadIdx.x;
    if (e >= nnz) return;
    {
        int pos = atomicAdd(cur_t + __ldg(tar_rows + e), 1);
        et[pos] = make_int2(__ldg(tar_cols + e), __float_as_int(__ldg(tar_vals + e)));
    }
    {
        int pos = atomicAdd(cur_s + __ldg(src_rows + e), 1);
        es[pos] = make_int2(__ldg(src_cols + e), __float_as_int(__ldg(src_vals + e)));
    }
}

// ---------------- gather SpMM (CSR, packed edges): Y[r] = sum v * X[c] ------
// 256-thread block = 4 groups of 64; each group owns one row, thread owns one f4
__global__ void __launch_bounds__(256) spmm_csr(
    const int* __restrict__ rowptr, const int2* __restrict__ edges,
    const float4* __restrict__ X, float4* __restrict__ Y)
{
    int row = blockIdx.x * 4 + (threadIdx.x >> 6);
    int g   = threadIdx.x & 63;
    int s = __ldg(rowptr + row), e = __ldg(rowptr + row + 1);
    float4 acc = make_float4(0.f, 0.f, 0.f, 0.f);
    int j = s;
    for (; j + 1 < e; j += 2) {
        int2 e0 = __ldcs(edges + j);
        int2 e1 = __ldcs(edges + j + 1);
        float v0 = __int_as_float(e0.y), v1 = __int_as_float(e1.y);
        float4 a0 = __ldg(X + (size_t)e0.x * D4 + g);
        float4 a1 = __ldg(X + (size_t)e1.x * D4 + g);
        acc.x = fmaf(v0, a0.x, acc.x); acc.y = fmaf(v0, a0.y, acc.y);
        acc.z = fmaf(v0, a0.z, acc.z); acc.w = fmaf(v0, a0.w, acc.w);
        acc.x = fmaf(v1, a1.x, acc.x); acc.y = fmaf(v1, a1.y, acc.y);
        acc.z = fmaf(v1, a1.z, acc.z); acc.w = fmaf(v1, a1.w, acc.w);
    }
    if (j < e) {
        int2 e0 = __ldcs(edges + j);
        float v0 = __int_as_float(e0.y);
        float4 a0 = __ldg(X + (size_t)e0.x * D4 + g);
        acc.x = fmaf(v0, a0.x, acc.x); acc.y = fmaf(v0, a0.y, acc.y);
        acc.z = fmaf(v0, a0.z, acc.z); acc.w = fmaf(v0, a0.w, acc.w);
    }
    Y[(size_t)row * D4 + g] = acc;
}

// ---------------- Threefry-2x32 (JAX partitionable random_bits) -------------
__device__ __forceinline__ uint32_t tf_bits(uint32_t k0, uint32_t k1,
                                            uint32_t k2, uint32_t ctr)
{
    uint32_t x0 = k0;
    uint32_t x1 = ctr + k1;
#define TFR(r) { x0 += x1; x1 = __funnelshift_l(x1, x1, (r)); x1 ^= x0; }
    TFR(13) TFR(15) TFR(26) TFR(6)    x0 += k1; x1 += k2 + 1u;
    TFR(17) TFR(29) TFR(16) TFR(24)   x0 += k2; x1 += k0 + 2u;
    TFR(13) TFR(15) TFR(26) TFR(6)    x0 += k0; x1 += k1 + 3u;
    TFR(17) TFR(29) TFR(16) TFR(24)   x0 += k1; x1 += k2 + 4u;
    TFR(13) TFR(15) TFR(26) TFR(6)    x0 += k2; x1 += k0 + 5u;
#undef TFR
    return x0 ^ x1;
}

// ------- gather SpMM fused with residual + dropout + accumulate + mean ------
// mode 0: x = drop(msg+poi); acc = poi + x
// mode 1: x = drop(msg+x);   acc += x
// mode 2: v = drop(msg+x);   out = (acc + v) * 0.25
__global__ void __launch_bounds__(256) spmm_csr_fused(
    const int* __restrict__ rowptr, const int2* __restrict__ edges,
    const float4* __restrict__ X,
    const float4* __restrict__ xprev, float4* __restrict__ xout,
    float4* __restrict__ accbuf, float4* __restrict__ out,
    uint32_t k0, uint32_t k1, int mode)
{
    int row = blockIdx.x * 4 + (threadIdx.x >> 6);
    int g   = threadIdx.x & 63;
    int s = __ldg(rowptr + row), e = __ldg(rowptr + row + 1);
    float4 m = make_float4(0.f, 0.f, 0.f, 0.f);
    int j = s;
    for (; j + 1 < e; j += 2) {
        int2 e0 = __ldcs(edges + j);
        int2 e1 = __ldcs(edges + j + 1);
        float v0 = __int_as_float(e0.y), v1 = __int_as_float(e1.y);
        float4 a0 = __ldg(X + (size_t)e0.x * D4 + g);
        float4 a1 = __ldg(X + (size_t)e1.x * D4 + g);
        m.x = fmaf(v0, a0.x, m.x); m.y = fmaf(v0, a0.y, m.y);
        m.z = fmaf(v0, a0.z, m.z); m.w = fmaf(v0, a0.w, m.w);
        m.x = fmaf(v1, a1.x, m.x); m.y = fmaf(v1, a1.y, m.y);
        m.z = fmaf(v1, a1.z, m.z); m.w = fmaf(v1, a1.w, m.w);
    }
    if (j < e) {
        int2 e0 = __ldcs(edges + j);
        float v0 = __int_as_float(e0.y);
        float4 a0 = __ldg(X + (size_t)e0.x * D4 + g);
        m.x = fmaf(v0, a0.x, m.x); m.y = fmaf(v0, a0.y, m.y);
        m.z = fmaf(v0, a0.z, m.z); m.w = fmaf(v0, a0.w, m.w);
    }

    size_t idx4 = (size_t)row * D4 + g;
    uint32_t base = (uint32_t)idx4 * 4u;
    uint32_t k2 = k0 ^ k1 ^ 0x1BD11BDAu;
    uint32_t b0 = tf_bits(k0, k1, k2, base + 0u);
    uint32_t b1 = tf_bits(k0, k1, k2, base + 1u);
    uint32_t b2 = tf_bits(k0, k1, k2, base + 2u);
    uint32_t b3 = tf_bits(k0, k1, k2, base + 3u);

    float4 p = xprev[idx4];
    float4 v;
    v.x = (b0 < THRESH) ? (m.x + p.x) * KEEP_INV : 0.0f;
    v.y = (b1 < THRESH) ? (m.y + p.y) * KEEP_INV : 0.0f;
    v.z = (b2 < THRESH) ? (m.z + p.z) * KEEP_INV : 0.0f;
    v.w = (b3 < THRESH) ? (m.w + p.w) * KEEP_INV : 0.0f;

    if (mode == 0) {
        xout[idx4] = v;
        accbuf[idx4] = make_float4(p.x + v.x, p.y + v.y, p.z + v.z, p.w + v.w);
    } else if (mode == 1) {
        xout[idx4] = v;
        float4 a = accbuf[idx4];
        accbuf[idx4] = make_float4(a.x + v.x, a.y + v.y, a.z + v.z, a.w + v.w);
    } else {
        float4 a = accbuf[idx4];
        out[idx4] = make_float4((a.x + v.x) * 0.25f, (a.y + v.y) * 0.25f,
                                (a.z + v.z) * 0.25f, (a.w + v.w) * 0.25f);
    }
}

// ---------------- host-side threefry (per-layer fold_in keys) ---------------
static inline unsigned h_rotl(unsigned x, int r) { return (x << r) | (x >> (32 - r)); }
static void host_threefry(unsigned k0, unsigned k1, unsigned x0, unsigned x1,
                          unsigned* o0, unsigned* o1)
{
    const int rots[2][4] = {{13, 15, 26, 6}, {17, 29, 16, 24}};
    unsigned ks[3] = {k0, k1, k0 ^ k1 ^ 0x1BD11BDAu};
    x0 += ks[0]; x1 += ks[1];
    for (int g = 0; g < 5; g++) {
        for (int j = 0; j < 4; j++) {
            x0 += x1; x1 = h_rotl(x1, rots[g & 1][j]); x1 ^= x0;
        }
        x0 += ks[(g + 1) % 3];
        x1 += ks[(g + 2) % 3] + (unsigned)(g + 1);
    }
    *o0 = x0; *o1 = x1;
}

extern "C" void kernel_launch(void* const* d_in, const int* in_sizes, int n_in,
                              void* d_out, int out_size)
{
    const float* poi     = (const float*)d_in[0];
    const int*   src_row = (const int*)  d_in[1];
    const int*   src_col = (const int*)  d_in[2];
    const float* src_val = (const float*)d_in[3];
    const int*   tar_row = (const int*)  d_in[4];
    const int*   tar_col = (const int*)  d_in[5];
    const float* tar_val = (const float*)d_in[6];
    int nnz = in_sizes[1];

    float4 *x, *mt, *acc;
    int *rp_s, *rp_t, *cur_s, *cur_t, *cnt;
    int2 *es, *et;
    cudaGetSymbolAddress((void**)&x,     g_x);
    cudaGetSymbolAddress((void**)&mt,    g_mt);
    cudaGetSymbolAddress((void**)&acc,   g_acc);
    cudaGetSymbolAddress((void**)&rp_s,  g_rp_src);
    cudaGetSymbolAddress((void**)&rp_t,  g_rp_tar);
    cudaGetSymbolAddress((void**)&cur_s, g_cur_src);
    cudaGetSymbolAddress((void**)&cur_t, g_cur_tar);
    cudaGetSymbolAddress((void**)&cnt,   g_cnt);
    cudaGetSymbolAddress((void**)&es,    g_e_src);
    cudaGetSymbolAddress((void**)&et,    g_e_tar);

    unsigned lk0[3], lk1[3];
    for (unsigned i = 0; i < 3; i++)
        host_threefry(0u, 42u, 0u, i, &lk0[i], &lk1[i]);

    int eb = (nnz + 255) / 256;
    int rb = NPOI / 4;               // 12500 blocks, 4 rows each

    // ---- fused CSR build for both matrices ----
    cudaMemsetAsync(cnt, 0, 2 * NPOI * sizeof(int), 0);
    hist2_kernel<<<eb, 256>>>(tar_row, src_row, cnt, nnz);
    scan2_kernel<<<2, 1024>>>(cnt, rp_t, cur_t, rp_s, cur_s);
    scatter2_kernel<<<eb, 256>>>(tar_row, tar_col, tar_val,
                                 src_row, src_col, src_val,
                                 cur_t, cur_s, et, es, nnz);

    // ---- 3 layers ----
    const float4* xin = (const float4*)poi;
    for (int i = 0; i < 3; i++) {
        spmm_csr<<<rb, 256>>>(rp_t, et, xin, mt);
        spmm_csr_fused<<<rb, 256>>>(rp_s, es, mt, xin,
                                    x, acc, (float4*)d_out, lk0[i], lk1[i], i);
        xin = (const float4*)x;
    }
}

// round 4
// speedup vs baseline: 3.0340x; 1.1384x over previous
#include <cuda_runtime.h>
#include <cuda_fp16.h>
#include <stdint.h>

// Problem constants (fixed by setup_inputs)
#define NPOI    50000
#define DIM     256
#define D4      (DIM / 4)            // 64 float4 per row (fp32)
#define D16     (DIM / 8)            // 32 uint4 per row (fp16: 8 halves per uint4)
#define NELEM   (NPOI * DIM)
#define NV4     (NELEM / 4)
#define NNZ_MAX 1600000
#define THRESH  0xE6666600u          // bits < THRESH <=> uniform(bits) < 0.9f
#define KEEP_INV (1.0f / 0.9f)

// ---------------- scratch (static device globals) ---------------------------
__device__ float4 g_x[NV4];            // layer activation x_i (fp32, residual path)
__device__ float4 g_acc[NV4];          // running sum of finals (fp32)
__device__ uint4  g_x16[NPOI * D16];   // x_i in fp16 (gather operand)
__device__ uint4  g_mt16[NPOI * D16];  // msg_tar in fp16 (gather operand)
__device__ int    g_rp_src[NPOI + 1], g_rp_tar[NPOI + 1];
__device__ int    g_cur_src[NPOI],   g_cur_tar[NPOI];
__device__ int    g_cnt[2 * NPOI];
__device__ int2   g_e_src[NNZ_MAX];    // packed (col, val-bits)
__device__ int2   g_e_tar[NNZ_MAX];

// ---------------- fp16 helpers ----------------------------------------------
__device__ __forceinline__ void acc8(float* a, float v, uint4 q)
{
    float2 f;
    f = __half22float2(*(__half2*)&q.x); a[0] = fmaf(v, f.x, a[0]); a[1] = fmaf(v, f.y, a[1]);
    f = __half22float2(*(__half2*)&q.y); a[2] = fmaf(v, f.x, a[2]); a[3] = fmaf(v, f.y, a[3]);
    f = __half22float2(*(__half2*)&q.z); a[4] = fmaf(v, f.x, a[4]); a[5] = fmaf(v, f.y, a[5]);
    f = __half22float2(*(__half2*)&q.w); a[6] = fmaf(v, f.x, a[6]); a[7] = fmaf(v, f.y, a[7]);
}

__device__ __forceinline__ uint4 pack8(const float* a)
{
    uint4 o;
    __half2 h;
    h = __floats2half2_rn(a[0], a[1]); o.x = *(uint32_t*)&h;
    h = __floats2half2_rn(a[2], a[3]); o.y = *(uint32_t*)&h;
    h = __floats2half2_rn(a[4], a[5]); o.z = *(uint32_t*)&h;
    h = __floats2half2_rn(a[6], a[7]); o.w = *(uint32_t*)&h;
    return o;
}

// ---------------- poi_embs fp32 -> fp16 --------------------------------------
__global__ void __launch_bounds__(256) cvt16_kernel(
    const float4* __restrict__ in, uint4* __restrict__ out)
{
    int t = blockIdx.x * 256 + threadIdx.x;   // one uint4 (8 halves) per thread
    if (t >= NPOI * D16) return;
    float4 a = in[t * 2], b = in[t * 2 + 1];
    float v[8] = {a.x, a.y, a.z, a.w, b.x, b.y, b.z, b.w};
    out[t] = pack8(v);
}

// ---------------- CSR build: fused histogram (both matrices) ----------------
__global__ void __launch_bounds__(256) hist2_kernel(
    const int* __restrict__ tar_rows, const int* __restrict__ src_rows,
    int* __restrict__ cnt, int nnz)
{
    int e = blockIdx.x * 256 + threadIdx.x;
    if (e >= nnz) return;
    atomicAdd(cnt + __ldg(tar_rows + e), 1);
    atomicAdd(cnt + NPOI + __ldg(src_rows + e), 1);
}

// ---------------- CSR build: 2-block exclusive scan -------------------------
__global__ void __launch_bounds__(1024) scan2_kernel(
    const int* __restrict__ cnt,
    int* __restrict__ rp_t, int* __restrict__ cur_t,
    int* __restrict__ rp_s, int* __restrict__ cur_s)
{
    const int* c  = (blockIdx.x == 0) ? cnt  : cnt + NPOI;
    int* rowptr   = (blockIdx.x == 0) ? rp_t : rp_s;
    int* cursor   = (blockIdx.x == 0) ? cur_t : cur_s;
    const int n = NPOI;

    __shared__ int carry;
    __shared__ int wsum[32];
    int tid = threadIdx.x, lane = tid & 31, wid = tid >> 5;
    if (tid == 0) carry = 0;
    __syncthreads();
    for (int base = 0; base < n; base += 1024) {
        int c0 = carry;
        int i = base + tid;
        int v = (i < n) ? c[i] : 0;
        int inc = v;
        #pragma unroll
        for (int o = 1; o < 32; o <<= 1) {
            int t = __shfl_up_sync(0xFFFFFFFFu, inc, o);
            if (lane >= o) inc += t;
        }
        if (lane == 31) wsum[wid] = inc;
        __syncthreads();
        if (wid == 0) {
            int s = wsum[lane];
            #pragma unroll
            for (int o = 1; o < 32; o <<= 1) {
                int t = __shfl_up_sync(0xFFFFFFFFu, s, o);
                if (lane >= o) s += t;
            }
            wsum[lane] = s;
        }
        __syncthreads();
        int block_incl = inc + (wid ? wsum[wid - 1] : 0);
        if (i < n) { int ex = c0 + block_incl - v; rowptr[i] = ex; cursor[i] = ex; }
        __syncthreads();
        if (tid == 1023) carry = c0 + block_incl;
        __syncthreads();
    }
    if (tid == 0) rowptr[n] = carry;
}

// ---------------- CSR build: fused scatter-permute (packed int2) ------------
__global__ void __launch_bounds__(256) scatter2_kernel(
    const int* __restrict__ tar_rows, const int* __restrict__ tar_cols,
    const float* __restrict__ tar_vals,
    const int* __restrict__ src_rows, const int* __restrict__ src_cols,
    const float* __restrict__ src_vals,
    int* __restrict__ cur_t, int* __restrict__ cur_s,
    int2* __restrict__ et, int2* __restrict__ es, int nnz)
{
    int e = blockIdx.x * 256 + threadIdx.x;
    if (e >= nnz) return;
    {
        int pos = atomicAdd(cur_t + __ldg(tar_rows + e), 1);
        et[pos] = make_int2(__ldg(tar_cols + e), __float_as_int(__ldg(tar_vals + e)));
    }
    {
        int pos = atomicAdd(cur_s + __ldg(src_rows + e), 1);
        es[pos] = make_int2(__ldg(src_cols + e), __float_as_int(__ldg(src_vals + e)));
    }
}

// ------- gather SpMM (CSR, fp16 operand): one warp per row ------------------
// lane owns 8 contiguous halves (16B); fp32 accumulate; fp16 output
__global__ void __launch_bounds__(256) spmm_h(
    const int* __restrict__ rowptr, const int2* __restrict__ edges,
    const uint4* __restrict__ X, uint4* __restrict__ Y)
{
    int row = blockIdx.x * 8 + (threadIdx.x >> 5);
    int g   = threadIdx.x & 31;
    int s = __ldg(rowptr + row), e = __ldg(rowptr + row + 1);
    float m[8] = {0.f, 0.f, 0.f, 0.f, 0.f, 0.f, 0.f, 0.f};
    int j = s;
    for (; j + 1 < e; j += 2) {
        int2 e0 = __ldcs(edges + j);
        int2 e1 = __ldcs(edges + j + 1);
        uint4 a0 = __ldg(X + (size_t)e0.x * D16 + g);
        uint4 a1 = __ldg(X + (size_t)e1.x * D16 + g);
        acc8(m, __int_as_float(e0.y), a0);
        acc8(m, __int_as_float(e1.y), a1);
    }
    if (j < e) {
        int2 e0 = __ldcs(edges + j);
        uint4 a0 = __ldg(X + (size_t)e0.x * D16 + g);
        acc8(m, __int_as_float(e0.y), a0);
    }
    Y[(size_t)row * D16 + g] = pack8(m);
}

// ---------------- Threefry-2x32 (JAX partitionable random_bits) -------------
__device__ __forceinline__ uint32_t tf_bits(uint32_t k0, uint32_t k1,
                                            uint32_t k2, uint32_t ctr)
{
    uint32_t x0 = k0;
    uint32_t x1 = ctr + k1;
#define TFR(r) { x0 += x1; x1 = __funnelshift_l(x1, x1, (r)); x1 ^= x0; }
    TFR(13) TFR(15) TFR(26) TFR(6)    x0 += k1; x1 += k2 + 1u;
    TFR(17) TFR(29) TFR(16) TFR(24)   x0 += k2; x1 += k0 + 2u;
    TFR(13) TFR(15) TFR(26) TFR(6)    x0 += k0; x1 += k1 + 3u;
    TFR(17) TFR(29) TFR(16) TFR(24)   x0 += k1; x1 += k2 + 4u;
    TFR(13) TFR(15) TFR(26) TFR(6)    x0 += k2; x1 += k0 + 5u;
#undef TFR
    return x0 ^ x1;
}

// --- gather SpMM (fp16 operand) fused with residual+dropout+acc(+mean) ------
// mode 0: x = drop(msg+poi); acc = poi + x      (xprev = poi fp32)
// mode 1: x = drop(msg+x);   acc += x
// mode 2: v = drop(msg+x);   out = (acc + v) * 0.25   (no x writes)
__global__ void __launch_bounds__(256) spmm_h_fused(
    const int* __restrict__ rowptr, const int2* __restrict__ edges,
    const uint4* __restrict__ X,
    const float4* __restrict__ xprev, float4* __restrict__ xout,
    uint4* __restrict__ xout16, float4* __restrict__ accbuf,
    float4* __restrict__ out, uint32_t k0, uint32_t k1, int mode)
{
    int row = blockIdx.x * 8 + (threadIdx.x >> 5);
    int g   = threadIdx.x & 31;
    int s = __ldg(rowptr + row), e = __ldg(rowptr + row + 1);
    float m[8] = {0.f, 0.f, 0.f, 0.f, 0.f, 0.f, 0.f, 0.f};
    int j = s;
    for (; j + 1 < e; j += 2) {
        int2 e0 = __ldcs(edges + j);
        int2 e1 = __ldcs(edges + j + 1);
        uint4 a0 = __ldg(X + (size_t)e0.x * D16 + g);
        uint4 a1 = __ldg(X + (size_t)e1.x * D16 + g);
        acc8(m, __int_as_float(e0.y), a0);
        acc8(m, __int_as_float(e1.y), a1);
    }
    if (j < e) {
        int2 e0 = __ldcs(edges + j);
        uint4 a0 = __ldg(X + (size_t)e0.x * D16 + g);
        acc8(m, __int_as_float(e0.y), a0);
    }

    // dropout mask: element indices row*256 + g*8 + {0..7}
    uint32_t base = (uint32_t)(row * DIM + g * 8);
    uint32_t k2 = k0 ^ k1 ^ 0x1BD11BDAu;
    size_t i4 = (size_t)row * D4 + g * 2;   // two float4 per lane
    float4 p0 = xprev[i4], p1 = xprev[i4 + 1];
    float pv[8] = {p0.x, p0.y, p0.z, p0.w, p1.x, p1.y, p1.z, p1.w};
    float v[8];
    #pragma unroll
    for (int t = 0; t < 8; t++) {
        uint32_t b = tf_bits(k0, k1, k2, base + (uint32_t)t);
        v[t] = (b < THRESH) ? (m[t] + pv[t]) * KEEP_INV : 0.0f;
    }
    float4 v0 = make_float4(v[0], v[1], v[2], v[3]);
    float4 v1 = make_float4(v[4], v[5], v[6], v[7]);

    if (mode == 0) {
        xout[i4] = v0; xout[i4 + 1] = v1;
        xout16[(size_t)row * D16 + g] = pack8(v);
        accbuf[i4]     = make_float4(p0.x + v0.x, p0.y + v0.y, p0.z + v0.z, p0.w + v0.w);
        accbuf[i4 + 1] = make_float4(p1.x + v1.x, p1.y + v1.y, p1.z + v1.z, p1.w + v1.w);
    } else if (mode == 1) {
        xout[i4] = v0; xout[i4 + 1] = v1;
        xout16[(size_t)row * D16 + g] = pack8(v);
        float4 a0 = accbuf[i4], a1 = accbuf[i4 + 1];
        accbuf[i4]     = make_float4(a0.x + v0.x, a0.y + v0.y, a0.z + v0.z, a0.w + v0.w);
        accbuf[i4 + 1] = make_float4(a1.x + v1.x, a1.y + v1.y, a1.z + v1.z, a1.w + v1.w);
    } else {
        float4 a0 = accbuf[i4], a1 = accbuf[i4 + 1];
        out[i4]     = make_float4((a0.x + v0.x) * 0.25f, (a0.y + v0.y) * 0.25f,
                                  (a0.z + v0.z) * 0.25f, (a0.w + v0.w) * 0.25f);
        out[i4 + 1] = make_float4((a1.x + v1.x) * 0.25f, (a1.y + v1.y) * 0.25f,
                                  (a1.z + v1.z) * 0.25f, (a1.w + v1.w) * 0.25f);
    }
}

// ---------------- host-side threefry (per-layer fold_in keys) ---------------
static inline unsigned h_rotl(unsigned x, int r) { return (x << r) | (x >> (32 - r)); }
static void host_threefry(unsigned k0, unsigned k1, unsigned x0, unsigned x1,
                          unsigned* o0, unsigned* o1)
{
    const int rots[2][4] = {{13, 15, 26, 6}, {17, 29, 16, 24}};
    unsigned ks[3] = {k0, k1, k0 ^ k1 ^ 0x1BD11BDAu};
    x0 += ks[0]; x1 += ks[1];
    for (int g = 0; g < 5; g++) {
        for (int j = 0; j < 4; j++) {
            x0 += x1; x1 = h_rotl(x1, rots[g & 1][j]); x1 ^= x0;
        }
        x0 += ks[(g + 1) % 3];
        x1 += ks[(g + 2) % 3] + (unsigned)(g + 1);
    }
    *o0 = x0; *o1 = x1;
}

extern "C" void kernel_launch(void* const* d_in, const int* in_sizes, int n_in,
                              void* d_out, int out_size)
{
    const float* poi     = (const float*)d_in[0];
    const int*   src_row = (const int*)  d_in[1];
    const int*   src_col = (const int*)  d_in[2];
    const float* src_val = (const float*)d_in[3];
    const int*   tar_row = (const int*)  d_in[4];
    const int*   tar_col = (const int*)  d_in[5];
    const float* tar_val = (const float*)d_in[6];
    int nnz = in_sizes[1];

    float4 *x, *acc;
    uint4 *x16, *mt16;
    int *rp_s, *rp_t, *cur_s, *cur_t, *cnt;
    int2 *es, *et;
    cudaGetSymbolAddress((void**)&x,     g_x);
    cudaGetSymbolAddress((void**)&acc,   g_acc);
    cudaGetSymbolAddress((void**)&x16,   g_x16);
    cudaGetSymbolAddress((void**)&mt16,  g_mt16);
    cudaGetSymbolAddress((void**)&rp_s,  g_rp_src);
    cudaGetSymbolAddress((void**)&rp_t,  g_rp_tar);
    cudaGetSymbolAddress((void**)&cur_s, g_cur_src);
    cudaGetSymbolAddress((void**)&cur_t, g_cur_tar);
    cudaGetSymbolAddress((void**)&cnt,   g_cnt);
    cudaGetSymbolAddress((void**)&es,    g_e_src);
    cudaGetSymbolAddress((void**)&et,    g_e_tar);

    unsigned lk0[3], lk1[3];
    for (unsigned i = 0; i < 3; i++)
        host_threefry(0u, 42u, 0u, i, &lk0[i], &lk1[i]);

    int eb = (nnz + 255) / 256;
    int rb = NPOI / 8;                       // warp per row, 8 rows per block
    int cb = (NPOI * D16 + 255) / 256;

    // ---- fused CSR build + fp16 snapshot of poi ----
    cudaMemsetAsync(cnt, 0, 2 * NPOI * sizeof(int), 0);
    cvt16_kernel<<<cb, 256>>>((const float4*)poi, x16);
    hist2_kernel<<<eb, 256>>>(tar_row, src_row, cnt, nnz);
    scan2_kernel<<<2, 1024>>>(cnt, rp_t, cur_t, rp_s, cur_s);
    scatter2_kernel<<<eb, 256>>>(tar_row, tar_col, tar_val,
                                 src_row, src_col, src_val,
                                 cur_t, cur_s, et, es, nnz);

    // ---- 3 layers ----
    const float4* xin_f32 = (const float4*)poi;
    for (int i = 0; i < 3; i++) {
        spmm_h<<<rb, 256>>>(rp_t, et, x16, mt16);
        spmm_h_fused<<<rb, 256>>>(rp_s, es, mt16, xin_f32,
                                  x, x16, acc, (float4*)d_out,
                                  lk0[i], lk1[i], i);
        xin_f32 = (const float4*)x;
    }
}

// round 6
// speedup vs baseline: 3.2718x; 1.0784x over previous
#include <cuda_runtime.h>
#include <cuda_fp16.h>
#include <stdint.h>

// Problem constants (fixed by setup_inputs)
#define NPOI    50000
#define DIM     256
#define D4      (DIM / 4)            // 64 float4 per row (fp32)
#define D16     (DIM / 8)            // 32 uint4 per row (fp16)
#define NELEM   (NPOI * DIM)
#define NV4     (NELEM / 4)
#define NNZ_MAX 1600000
#define THRESH  0xE6666600u          // bits < THRESH <=> uniform(bits) < 0.9f
#define KEEP_INV (1.0f / 0.9f)
#define SPLIT   32768                // rows < SPLIT: mask precomputed in spmm_h

// ---------------- scratch (static device globals) ---------------------------
__device__ float4  g_x[NV4];            // layer activation x_i (fp32 residual)
__device__ float4  g_acc[NV4];          // running sum of finals (fp32)
__device__ uint4   g_x16[NPOI * D16];   // x_i in fp16 (gather operand)
__device__ uint4   g_mt16[NPOI * D16];  // msg_tar in fp16 (gather operand)
__device__ uint8_t g_mask[NELEM / 8];   // dropout mask bits, rows < SPLIT
__device__ int     g_rp_src[NPOI + 1], g_rp_tar[NPOI + 1];
__device__ int     g_cnt[2 * NPOI];
__device__ int     g_rank_t[NNZ_MAX], g_rank_s[NNZ_MAX];
__device__ int2    g_e_src[NNZ_MAX];    // packed (col, val-bits)
__device__ int2    g_e_tar[NNZ_MAX];

// ---------------- fp16 helpers ----------------------------------------------
__device__ __forceinline__ void acc8(float* a, float v, uint4 q)
{
    float2 f;
    f = __half22float2(*(__half2*)&q.x); a[0] = fmaf(v, f.x, a[0]); a[1] = fmaf(v, f.y, a[1]);
    f = __half22float2(*(__half2*)&q.y); a[2] = fmaf(v, f.x, a[2]); a[3] = fmaf(v, f.y, a[3]);
    f = __half22float2(*(__half2*)&q.z); a[4] = fmaf(v, f.x, a[4]); a[5] = fmaf(v, f.y, a[5]);
    f = __half22float2(*(__half2*)&q.w); a[6] = fmaf(v, f.x, a[6]); a[7] = fmaf(v, f.y, a[7]);
}

__device__ __forceinline__ uint4 pack8(const float* a)
{
    uint4 o;
    __half2 h;
    h = __floats2half2_rn(a[0], a[1]); o.x = *(uint32_t*)&h;
    h = __floats2half2_rn(a[2], a[3]); o.y = *(uint32_t*)&h;
    h = __floats2half2_rn(a[4], a[5]); o.z = *(uint32_t*)&h;
    h = __floats2half2_rn(a[6], a[7]); o.w = *(uint32_t*)&h;
    return o;
}

// ---------------- Threefry-2x32 (JAX partitionable random_bits) -------------
__device__ __forceinline__ uint32_t tf_bits(uint32_t k0, uint32_t k1,
                                            uint32_t k2, uint32_t ctr)
{
    uint32_t x0 = k0;
    uint32_t x1 = ctr + k1;
#define TFR(r) { x0 += x1; x1 = __funnelshift_l(x1, x1, (r)); x1 ^= x0; }
    TFR(13) TFR(15) TFR(26) TFR(6)    x0 += k1; x1 += k2 + 1u;
    TFR(17) TFR(29) TFR(16) TFR(24)   x0 += k2; x1 += k0 + 2u;
    TFR(13) TFR(15) TFR(26) TFR(6)    x0 += k0; x1 += k1 + 3u;
    TFR(17) TFR(29) TFR(16) TFR(24)   x0 += k1; x1 += k2 + 4u;
    TFR(13) TFR(15) TFR(26) TFR(6)    x0 += k2; x1 += k0 + 5u;
#undef TFR
    return x0 ^ x1;
}

__device__ __forceinline__ uint32_t mask8(uint32_t k0, uint32_t k1,
                                          uint32_t k2, uint32_t base)
{
    uint32_t m = 0;
    #pragma unroll
    for (int t = 0; t < 8; t++)
        m |= (tf_bits(k0, k1, k2, base + (uint32_t)t) < THRESH) ? (1u << t) : 0u;
    return m;
}

// ---------------- poi_embs fp32 -> fp16 --------------------------------------
__global__ void __launch_bounds__(256) cvt16_kernel(
    const float4* __restrict__ in, uint4* __restrict__ out)
{
    int t = blockIdx.x * 256 + threadIdx.x;
    if (t >= NPOI * D16) return;
    float4 a = in[t * 2], b = in[t * 2 + 1];
    float v[8] = {a.x, a.y, a.z, a.w, b.x, b.y, b.z, b.w};
    out[t] = pack8(v);
}

// ------- CSR build: histogram, keeping the atomic return as the edge rank ---
__global__ void __launch_bounds__(256) hist2_kernel(
    const int* __restrict__ tar_rows, const int* __restrict__ src_rows,
    int* __restrict__ cnt, int* __restrict__ rank_t, int* __restrict__ rank_s,
    int nnz)
{
    int e = blockIdx.x * 256 + threadIdx.x;
    if (e >= nnz) return;
    int rt = atomicAdd(cnt + __ldg(tar_rows + e), 1);
    int rs = atomicAdd(cnt + NPOI + __ldg(src_rows + e), 1);
    __stcs(rank_t + e, rt);
    __stcs(rank_s + e, rs);
}

// ---------------- CSR build: 2-block exclusive scan -------------------------
__global__ void __launch_bounds__(1024) scan2_kernel(
    const int* __restrict__ cnt, int* __restrict__ rp_t, int* __restrict__ rp_s)
{
    const int* c  = (blockIdx.x == 0) ? cnt  : cnt + NPOI;
    int* rowptr   = (blockIdx.x == 0) ? rp_t : rp_s;
    const int n = NPOI;

    __shared__ int carry;
    __shared__ int wsum[32];
    int tid = threadIdx.x, lane = tid & 31, wid = tid >> 5;
    if (tid == 0) carry = 0;
    __syncthreads();
    for (int base = 0; base < n; base += 1024) {
        int c0 = carry;
        int i = base + tid;
        int v = (i < n) ? c[i] : 0;
        int inc = v;
        #pragma unroll
        for (int o = 1; o < 32; o <<= 1) {
            int t = __shfl_up_sync(0xFFFFFFFFu, inc, o);
            if (lane >= o) inc += t;
        }
        if (lane == 31) wsum[wid] = inc;
        __syncthreads();
        if (wid == 0) {
            int s = wsum[lane];
            #pragma unroll
            for (int o = 1; o < 32; o <<= 1) {
                int t = __shfl_up_sync(0xFFFFFFFFu, s, o);
                if (lane >= o) s += t;
            }
            wsum[lane] = s;
        }
        __syncthreads();
        int block_incl = inc + (wid ? wsum[wid - 1] : 0);
        if (i < n) rowptr[i] = c0 + block_incl - v;
        __syncthreads();
        if (tid == 1023) carry = c0 + block_incl;
        __syncthreads();
    }
    if (tid == 0) rowptr[n] = carry;
}

// --------- CSR build: rank-based scatter-permute (no atomics) ---------------
__global__ void __launch_bounds__(256) scatter2_kernel(
    const int* __restrict__ tar_rows, const int* __restrict__ tar_cols,
    const float* __restrict__ tar_vals,
    const int* __restrict__ src_rows, const int* __restrict__ src_cols,
    const float* __restrict__ src_vals,
    const int* __restrict__ rp_t, const int* __restrict__ rp_s,
    const int* __restrict__ rank_t, const int* __restrict__ rank_s,
    int2* __restrict__ et, int2* __restrict__ es, int nnz)
{
    int e = blockIdx.x * 256 + threadIdx.x;
    if (e >= nnz) return;
    {
        int pos = __ldg(rp_t + __ldg(tar_rows + e)) + __ldcs(rank_t + e);
        et[pos] = make_int2(__ldg(tar_cols + e), __float_as_int(__ldg(tar_vals + e)));
    }
    {
        int pos = __ldg(rp_s + __ldg(src_rows + e)) + __ldcs(rank_s + e);
        es[pos] = make_int2(__ldg(src_cols + e), __float_as_int(__ldg(src_vals + e)));
    }
}

// ------- tar SpMM (fp16 operand) + dropout-mask precompute ------------------
// warp per row; lane owns 8 halves; also emits mask byte for rows < SPLIT
__global__ void __launch_bounds__(256) spmm_h(
    const int* __restrict__ rowptr, const int2* __restrict__ edges,
    const uint4* __restrict__ X, uint4* __restrict__ Y,
    uint8_t* __restrict__ maskbuf, uint32_t k0, uint32_t k1)
{
    int row = blockIdx.x * 8 + (threadIdx.x >> 5);
    int g   = threadIdx.x & 31;
    int s = __ldg(rowptr + row), e = __ldg(rowptr + row + 1);
    float m[8] = {0.f, 0.f, 0.f, 0.f, 0.f, 0.f, 0.f, 0.f};
    int j = s;
    for (; j + 3 < e; j += 4) {
        int2 e0 = __ldcs(edges + j),     e1 = __ldcs(edges + j + 1);
        int2 e2 = __ldcs(edges + j + 2), e3 = __ldcs(edges + j + 3);
        uint4 a0 = __ldg(X + (size_t)e0.x * D16 + g);
        uint4 a1 = __ldg(X + (size_t)e1.x * D16 + g);
        uint4 a2 = __ldg(X + (size_t)e2.x * D16 + g);
        uint4 a3 = __ldg(X + (size_t)e3.x * D16 + g);
        acc8(m, __int_as_float(e0.y), a0);
        acc8(m, __int_as_float(e1.y), a1);
        acc8(m, __int_as_float(e2.y), a2);
        acc8(m, __int_as_float(e3.y), a3);
    }
    for (; j < e; j++) {
        int2 e0 = __ldcs(edges + j);
        uint4 a0 = __ldg(X + (size_t)e0.x * D16 + g);
        acc8(m, __int_as_float(e0.y), a0);
    }
    Y[(size_t)row * D16 + g] = pack8(m);

    if (row < SPLIT) {
        uint32_t k2 = k0 ^ k1 ^ 0x1BD11BDAu;
        maskbuf[row * 32 + g] =
            (uint8_t)mask8(k0, k1, k2, (uint32_t)(row * DIM + g * 8));
    }
}

// --- src SpMM fused with residual+dropout+acc(+mean); mask read or inline ---
// mode 0: x = drop(msg+poi); acc = poi + x
// mode 1: x = drop(msg+x);   acc += x
// mode 2: v = drop(msg+x);   out = (acc + v) * 0.25
__global__ void __launch_bounds__(256) spmm_h_fused(
    const int* __restrict__ rowptr, const int2* __restrict__ edges,
    const uint4* __restrict__ X, const uint8_t* __restrict__ maskbuf,
    const float4* __restrict__ xprev, float4* __restrict__ xout,
    uint4* __restrict__ xout16, float4* __restrict__ accbuf,
    float4* __restrict__ out, uint32_t k0, uint32_t k1, int mode)
{
    int row = blockIdx.x * 8 + (threadIdx.x >> 5);
    int g   = threadIdx.x & 31;
    int s = __ldg(rowptr + row), e = __ldg(rowptr + row + 1);

    // mask byte: precomputed for rows < SPLIT, inline threefry otherwise
    uint32_t m8;
    if (row < SPLIT) {
        m8 = maskbuf[row * 32 + g];
    } else {
        uint32_t k2 = k0 ^ k1 ^ 0x1BD11BDAu;
        m8 = mask8(k0, k1, k2, (uint32_t)(row * DIM + g * 8));
    }

    float m[8] = {0.f, 0.f, 0.f, 0.f, 0.f, 0.f, 0.f, 0.f};
    int j = s;
    for (; j + 3 < e; j += 4) {
        int2 e0 = __ldcs(edges + j),     e1 = __ldcs(edges + j + 1);
        int2 e2 = __ldcs(edges + j + 2), e3 = __ldcs(edges + j + 3);
        uint4 a0 = __ldg(X + (size_t)e0.x * D16 + g);
        uint4 a1 = __ldg(X + (size_t)e1.x * D16 + g);
        uint4 a2 = __ldg(X + (size_t)e2.x * D16 + g);
        uint4 a3 = __ldg(X + (size_t)e3.x * D16 + g);
        acc8(m, __int_as_float(e0.y), a0);
        acc8(m, __int_as_float(e1.y), a1);
        acc8(m, __int_as_float(e2.y), a2);
        acc8(m, __int_as_float(e3.y), a3);
    }
    for (; j < e; j++) {
        int2 e0 = __ldcs(edges + j);
        uint4 a0 = __ldg(X + (size_t)e0.x * D16 + g);
        acc8(m, __int_as_float(e0.y), a0);
    }

    size_t i4 = (size_t)row * D4 + g * 2;
    float4 p0 = xprev[i4], p1 = xprev[i4 + 1];
    float pv[8] = {p0.x, p0.y, p0.z, p0.w, p1.x, p1.y, p1.z, p1.w};
    float v[8];
    #pragma unroll
    for (int t = 0; t < 8; t++)
        v[t] = ((m8 >> t) & 1u) ? (m[t] + pv[t]) * KEEP_INV : 0.0f;
    float4 v0 = make_float4(v[0], v[1], v[2], v[3]);
    float4 v1 = make_float4(v[4], v[5], v[6], v[7]);

    if (mode == 0) {
        xout[i4] = v0; xout[i4 + 1] = v1;
        xout16[(size_t)row * D16 + g] = pack8(v);
        accbuf[i4]     = make_float4(p0.x + v0.x, p0.y + v0.y, p0.z + v0.z, p0.w + v0.w);
        accbuf[i4 + 1] = make_float4(p1.x + v1.x, p1.y + v1.y, p1.z + v1.z, p1.w + v1.w);
    } else if (mode == 1) {
        xout[i4] = v0; xout[i4 + 1] = v1;
        xout16[(size_t)row * D16 + g] = pack8(v);
        float4 a0 = accbuf[i4], a1 = accbuf[i4 + 1];
        accbuf[i4]     = make_float4(a0.x + v0.x, a0.y + v0.y, a0.z + v0.z, a0.w + v0.w);
        accbuf[i4 + 1] = make_float4(a1.x + v1.x, a1.y + v1.y, a1.z + v1.z, a1.w + v1.w);
    } else {
        float4 a0 = accbuf[i4], a1 = accbuf[i4 + 1];
        out[i4]     = make_float4((a0.x + v0.x) * 0.25f, (a0.y + v0.y) * 0.25f,
                                  (a0.z + v0.z) * 0.25f, (a0.w + v0.w) * 0.25f);
        out[i4 + 1] = make_float4((a1.x + v1.x) * 0.25f, (a1.y + v1.y) * 0.25f,
                                  (a1.z + v1.z) * 0.25f, (a1.w + v1.w) * 0.25f);
    }
}

// ---------------- host-side threefry (per-layer fold_in keys) ---------------
static inline unsigned h_rotl(unsigned x, int r) { return (x << r) | (x >> (32 - r)); }
static void host_threefry(unsigned k0, unsigned k1, unsigned x0, unsigned x1,
                          unsigned* o0, unsigned* o1)
{
    const int rots[2][4] = {{13, 15, 26, 6}, {17, 29, 16, 24}};
    unsigned ks[3] = {k0, k1, k0 ^ k1 ^ 0x1BD11BDAu};
    x0 += ks[0]; x1 += ks[1];
    for (int g = 0; g < 5; g++) {
        for (int j = 0; j < 4; j++) {
            x0 += x1; x1 = h_rotl(x1, rots[g & 1][j]); x1 ^= x0;
        }
        x0 += ks[(g + 1) % 3];
        x1 += ks[(g + 2) % 3] + (unsigned)(g + 1);
    }
    *o0 = x0; *o1 = x1;
}

extern "C" void kernel_launch(void* const* d_in, const int* in_sizes, int n_in,
                              void* d_out, int out_size)
{
    const float* poi     = (const float*)d_in[0];
    const int*   src_row = (const int*)  d_in[1];
    const int*   src_col = (const int*)  d_in[2];
    const float* src_val = (const float*)d_in[3];
    const int*   tar_row = (const int*)  d_in[4];
    const int*   tar_col = (const int*)  d_in[5];
    const float* tar_val = (const float*)d_in[6];
    int nnz = in_sizes[1];

    float4 *x, *acc;
    uint4 *x16, *mt16;
    uint8_t *mask;
    int *rp_s, *rp_t, *cnt, *rank_t, *rank_s;
    int2 *es, *et;
    cudaGetSymbolAddress((void**)&x,      g_x);
    cudaGetSymbolAddress((void**)&acc,    g_acc);
    cudaGetSymbolAddress((void**)&x16,    g_x16);
    cudaGetSymbolAddress((void**)&mt16,   g_mt16);
    cudaGetSymbolAddress((void**)&mask,   g_mask);
    cudaGetSymbolAddress((void**)&rp_s,   g_rp_src);
    cudaGetSymbolAddress((void**)&rp_t,   g_rp_tar);
    cudaGetSymbolAddress((void**)&cnt,    g_cnt);
    cudaGetSymbolAddress((void**)&rank_t, g_rank_t);
    cudaGetSymbolAddress((void**)&rank_s, g_rank_s);
    cudaGetSymbolAddress((void**)&es,     g_e_src);
    cudaGetSymbolAddress((void**)&et,     g_e_tar);

    unsigned lk0[3], lk1[3];
    for (unsigned i = 0; i < 3; i++)
        host_threefry(0u, 42u, 0u, i, &lk0[i], &lk1[i]);

    int eb = (nnz + 255) / 256;
    int rb = NPOI / 8;
    int cb = (NPOI * D16 + 255) / 256;

    // ---- fused CSR build (rank-based, atomic only in hist) + fp16 snapshot -
    cudaMemsetAsync(cnt, 0, 2 * NPOI * sizeof(int), 0);
    cvt16_kernel<<<cb, 256>>>((const float4*)poi, x16);
    hist2_kernel<<<eb, 256>>>(tar_row, src_row, cnt, rank_t, rank_s, nnz);
    scan2_kernel<<<2, 1024>>>(cnt, rp_t, rp_s);
    scatter2_kernel<<<eb, 256>>>(tar_row, tar_col, tar_val,
                                 src_row, src_col, src_val,
                                 rp_t, rp_s, rank_t, rank_s, et, es, nnz);

    // ---- 3 layers ----
    const float4* xin_f32 = (const float4*)poi;
    for (int i = 0; i < 3; i++) {
        spmm_h<<<rb, 256>>>(rp_t, et, x16, mt16, mask, lk0[i], lk1[i]);
        spmm_h_fused<<<rb, 256>>>(rp_s, es, mt16, mask, xin_f32,
                                  x, x16, acc, (float4*)d_out,
                                  lk0[i], lk1[i], i);
        xin_f32 = (const float4*)x;
    }
}

// round 7
// speedup vs baseline: 3.5498x; 1.0850x over previous
#include <cuda_runtime.h>
#include <cuda_fp16.h>
#include <stdint.h>

// Problem constants (fixed by setup_inputs)
#define NPOI    50000
#define DIM     256
#define D4      (DIM / 4)            // 64 float4 per row (fp32)
#define D16     (DIM / 8)            // 32 uint4 per row (fp16)
#define NELEM   (NPOI * DIM)
#define NV4     (NELEM / 4)
#define NNZ_MAX 1600000
#define MASKB   (NELEM / 8)          // mask bytes per layer (1.6M)
#define THRESH  0xE6666600u          // bits < THRESH <=> uniform(bits) < 0.9f
#define KEEP_INV (1.0f / 0.9f)
// mask-generation row ranges (who computes which rows' dropout masks)
#define M1      6016                 // [0,M1)    x3 layers -> hist2
#define M2      17024                // [M1,M2)   x3 layers -> scatter2
#define M3      31488                // [M2,M3)   per layer -> spmm_h
                                     // [M3,NPOI) per layer -> fused inline

// ---------------- scratch (static device globals) ---------------------------
__device__ float4  g_acc[NV4];          // running sum of finals (fp32)
__device__ uint4   g_x16[NPOI * D16];   // x_i in fp16 (gather + residual)
__device__ uint4   g_mt16[NPOI * D16];  // msg_tar in fp16 (gather operand)
__device__ uint8_t g_mask[3 * MASKB];   // dropout mask bits, 3 layers
__device__ int     g_rp_src[NPOI + 1], g_rp_tar[NPOI + 1];
__device__ int     g_cnt[2 * NPOI];
__device__ int     g_rank_t[NNZ_MAX], g_rank_s[NNZ_MAX];
__device__ int2    g_e_src[NNZ_MAX];    // packed (col, val-bits)
__device__ int2    g_e_tar[NNZ_MAX];

// ---------------- fp16 helpers ----------------------------------------------
__device__ __forceinline__ void acc8(float* a, float v, uint4 q)
{
    float2 f;
    f = __half22float2(*(__half2*)&q.x); a[0] = fmaf(v, f.x, a[0]); a[1] = fmaf(v, f.y, a[1]);
    f = __half22float2(*(__half2*)&q.y); a[2] = fmaf(v, f.x, a[2]); a[3] = fmaf(v, f.y, a[3]);
    f = __half22float2(*(__half2*)&q.z); a[4] = fmaf(v, f.x, a[4]); a[5] = fmaf(v, f.y, a[5]);
    f = __half22float2(*(__half2*)&q.w); a[6] = fmaf(v, f.x, a[6]); a[7] = fmaf(v, f.y, a[7]);
}

__device__ __forceinline__ void unpack8(float* f, uint4 q)
{
    float2 t;
    t = __half22float2(*(__half2*)&q.x); f[0] = t.x; f[1] = t.y;
    t = __half22float2(*(__half2*)&q.y); f[2] = t.x; f[3] = t.y;
    t = __half22float2(*(__half2*)&q.z); f[4] = t.x; f[5] = t.y;
    t = __half22float2(*(__half2*)&q.w); f[6] = t.x; f[7] = t.y;
}

__device__ __forceinline__ uint4 pack8(const float* a)
{
    uint4 o;
    __half2 h;
    h = __floats2half2_rn(a[0], a[1]); o.x = *(uint32_t*)&h;
    h = __floats2half2_rn(a[2], a[3]); o.y = *(uint32_t*)&h;
    h = __floats2half2_rn(a[4], a[5]); o.z = *(uint32_t*)&h;
    h = __floats2half2_rn(a[6], a[7]); o.w = *(uint32_t*)&h;
    return o;
}

// ---------------- Threefry-2x32 (JAX partitionable random_bits) -------------
__device__ __forceinline__ uint32_t tf_bits(uint32_t k0, uint32_t k1,
                                            uint32_t k2, uint32_t ctr)
{
    uint32_t x0 = k0;
    uint32_t x1 = ctr + k1;
#define TFR(r) { x0 += x1; x1 = __funnelshift_l(x1, x1, (r)); x1 ^= x0; }
    TFR(13) TFR(15) TFR(26) TFR(6)    x0 += k1; x1 += k2 + 1u;
    TFR(17) TFR(29) TFR(16) TFR(24)   x0 += k2; x1 += k0 + 2u;
    TFR(13) TFR(15) TFR(26) TFR(6)    x0 += k0; x1 += k1 + 3u;
    TFR(17) TFR(29) TFR(16) TFR(24)   x0 += k1; x1 += k2 + 4u;
    TFR(13) TFR(15) TFR(26) TFR(6)    x0 += k2; x1 += k0 + 5u;
#undef TFR
    return x0 ^ x1;
}

__device__ __forceinline__ uint32_t mask8(uint32_t k0, uint32_t k1,
                                          uint32_t k2, uint32_t base)
{
    uint32_t m = 0;
    #pragma unroll
    for (int t = 0; t < 8; t++)
        m |= (tf_bits(k0, k1, k2, base + (uint32_t)t) < THRESH) ? (1u << t) : 0u;
    return m;
}

// per-layer key select (layer in {0,1,2})
__device__ __forceinline__ void pick_key(int layer,
    uint32_t a0, uint32_t b0, uint32_t a1, uint32_t b1,
    uint32_t a2, uint32_t b2, uint32_t* k0, uint32_t* k1)
{
    *k0 = (layer == 0) ? a0 : (layer == 1) ? a1 : a2;
    *k1 = (layer == 0) ? b0 : (layer == 1) ? b1 : b2;
}

// ---------------- poi_embs fp32 -> fp16 --------------------------------------
__global__ void __launch_bounds__(256) cvt16_kernel(
    const float4* __restrict__ in, uint4* __restrict__ out)
{
    int t = blockIdx.x * 256 + threadIdx.x;
    if (t >= NPOI * D16) return;
    float4 a = in[t * 2], b = in[t * 2 + 1];
    float v[8] = {a.x, a.y, a.z, a.w, b.x, b.y, b.z, b.w};
    out[t] = pack8(v);
}

// ------- CSR build: histogram (rank = atomic return) + mask rows [0,M1) -----
__global__ void __launch_bounds__(256) hist2_kernel(
    const int* __restrict__ tar_rows, const int* __restrict__ src_rows,
    int* __restrict__ cnt, int* __restrict__ rank_t, int* __restrict__ rank_s,
    uint8_t* __restrict__ mask, int nnz,
    uint32_t a0, uint32_t b0, uint32_t a1, uint32_t b1, uint32_t a2, uint32_t b2)
{
    int t = blockIdx.x * 256 + threadIdx.x;
    if (t < nnz) {
        int rt = atomicAdd(cnt + __ldg(tar_rows + t), 1);
        int rs = atomicAdd(cnt + NPOI + __ldg(src_rows + t), 1);
        __stcs(rank_t + t, rt);
        __stcs(rank_s + t, rs);
    }
    if (t < 3 * M1 * 32) {
        int layer = t / (M1 * 32);
        int r     = t - layer * (M1 * 32);     // byte index = row*32+g, row<M1
        uint32_t k0, k1;
        pick_key(layer, a0, b0, a1, b1, a2, b2, &k0, &k1);
        uint32_t k2 = k0 ^ k1 ^ 0x1BD11BDAu;
        mask[layer * MASKB + r] = (uint8_t)mask8(k0, k1, k2, (uint32_t)r * 8u);
    }
}

// ---------------- CSR build: 2-block exclusive scan -------------------------
__global__ void __launch_bounds__(1024) scan2_kernel(
    const int* __restrict__ cnt, int* __restrict__ rp_t, int* __restrict__ rp_s)
{
    const int* c  = (blockIdx.x == 0) ? cnt  : cnt + NPOI;
    int* rowptr   = (blockIdx.x == 0) ? rp_t : rp_s;
    const int n = NPOI;

    __shared__ int carry;
    __shared__ int wsum[32];
    int tid = threadIdx.x, lane = tid & 31, wid = tid >> 5;
    if (tid == 0) carry = 0;
    __syncthreads();
    for (int base = 0; base < n; base += 1024) {
        int c0 = carry;
        int i = base + tid;
        int v = (i < n) ? c[i] : 0;
        int inc = v;
        #pragma unroll
        for (int o = 1; o < 32; o <<= 1) {
            int t = __shfl_up_sync(0xFFFFFFFFu, inc, o);
            if (lane >= o) inc += t;
        }
        if (lane == 31) wsum[wid] = inc;
        __syncthreads();
        if (wid == 0) {
            int s = wsum[lane];
            #pragma unroll
            for (int o = 1; o < 32; o <<= 1) {
                int t = __shfl_up_sync(0xFFFFFFFFu, s, o);
                if (lane >= o) s += t;
            }
            wsum[lane] = s;
        }
        __syncthreads();
        int block_incl = inc + (wid ? wsum[wid - 1] : 0);
        if (i < n) rowptr[i] = c0 + block_incl - v;
        __syncthreads();
        if (tid == 1023) carry = c0 + block_incl;
        __syncthreads();
    }
    if (tid == 0) rowptr[n] = carry;
}

// --- CSR build: rank-based scatter (no atomics) + mask rows [M1,M2) ---------
__global__ void __launch_bounds__(256) scatter2_kernel(
    const int* __restrict__ tar_rows, const int* __restrict__ tar_cols,
    const float* __restrict__ tar_vals,
    const int* __restrict__ src_rows, const int* __restrict__ src_cols,
    const float* __restrict__ src_vals,
    const int* __restrict__ rp_t, const int* __restrict__ rp_s,
    const int* __restrict__ rank_t, const int* __restrict__ rank_s,
    int2* __restrict__ et, int2* __restrict__ es,
    uint8_t* __restrict__ mask, int nnz,
    uint32_t a0, uint32_t b0, uint32_t a1, uint32_t b1, uint32_t a2, uint32_t b2)
{
    int t = blockIdx.x * 256 + threadIdx.x;
    if (t < nnz) {
        {
            int pos = __ldg(rp_t + __ldg(tar_rows + t)) + __ldcs(rank_t + t);
            et[pos] = make_int2(__ldg(tar_cols + t), __float_as_int(__ldg(tar_vals + t)));
        }
        {
            int pos = __ldg(rp_s + __ldg(src_rows + t)) + __ldcs(rank_s + t);
            es[pos] = make_int2(__ldg(src_cols + t), __float_as_int(__ldg(src_vals + t)));
        }
    }
    const int RANGE = (M2 - M1) * 32;
    if (t < 3 * RANGE) {
        int layer = t / RANGE;
        int r     = M1 * 32 + (t - layer * RANGE);  // byte index, row in [M1,M2)
        uint32_t k0, k1;
        pick_key(layer, a0, b0, a1, b1, a2, b2, &k0, &k1);
        uint32_t k2 = k0 ^ k1 ^ 0x1BD11BDAu;
        mask[layer * MASKB + r] = (uint8_t)mask8(k0, k1, k2, (uint32_t)r * 8u);
    }
}

// ------- tar SpMM (fp16 operand) + mask rows [M2,M3) for this layer ---------
// warp per row; lane owns 8 halves
__global__ void __launch_bounds__(256) spmm_h(
    const int* __restrict__ rowptr, const int2* __restrict__ edges,
    const uint4* __restrict__ X, uint4* __restrict__ Y,
    uint8_t* __restrict__ maskL, uint32_t k0, uint32_t k1)
{
    int row = blockIdx.x * 8 + (threadIdx.x >> 5);
    int g   = threadIdx.x & 31;
    int s = __ldg(rowptr + row), e = __ldg(rowptr + row + 1);
    float m[8] = {0.f, 0.f, 0.f, 0.f, 0.f, 0.f, 0.f, 0.f};
    int j = s;
    for (; j + 3 < e; j += 4) {
        int2 e0 = __ldcs(edges + j),     e1 = __ldcs(edges + j + 1);
        int2 e2 = __ldcs(edges + j + 2), e3 = __ldcs(edges + j + 3);
        uint4 a0 = __ldg(X + (size_t)e0.x * D16 + g);
        uint4 a1 = __ldg(X + (size_t)e1.x * D16 + g);
        uint4 a2 = __ldg(X + (size_t)e2.x * D16 + g);
        uint4 a3 = __ldg(X + (size_t)e3.x * D16 + g);
        acc8(m, __int_as_float(e0.y), a0);
        acc8(m, __int_as_float(e1.y), a1);
        acc8(m, __int_as_float(e2.y), a2);
        acc8(m, __int_as_float(e3.y), a3);
    }
    for (; j < e; j++) {
        int2 e0 = __ldcs(edges + j);
        uint4 a0 = __ldg(X + (size_t)e0.x * D16 + g);
        acc8(m, __int_as_float(e0.y), a0);
    }
    Y[(size_t)row * D16 + g] = pack8(m);

    if (row >= M2 && row < M3) {
        uint32_t k2 = k0 ^ k1 ^ 0x1BD11BDAu;
        uint32_t r = (uint32_t)(row * 32 + g);
        maskL[r] = (uint8_t)mask8(k0, k1, k2, r * 8u);
    }
}

// --- src SpMM fused: residual(fp16)+dropout+acc(+mean); mask read or inline -
// mode 0: x16 = drop(msg+poi);  acc = poi + v       (poi fp32)
// mode 1: x16 = drop(msg+x16);  acc += v
// mode 2: v = drop(msg+x16);    out = (acc + v) * 0.25
__global__ void __launch_bounds__(256) spmm_h_fused(
    const int* __restrict__ rowptr, const int2* __restrict__ edges,
    const uint4* __restrict__ X, const uint8_t* __restrict__ maskL,
    const float4* __restrict__ poi, const uint4* __restrict__ xprev16,
    uint4* __restrict__ xout16, float4* __restrict__ accbuf,
    float4* __restrict__ out, uint32_t k0, uint32_t k1, int mode)
{
    int row = blockIdx.x * 8 + (threadIdx.x >> 5);
    int g   = threadIdx.x & 31;
    int s = __ldg(rowptr + row), e = __ldg(rowptr + row + 1);

    // mask byte: precomputed for rows < M3, inline threefry for the tail
    uint32_t m8;
    if (row < M3) {
        m8 = maskL[row * 32 + g];
    } else {
        uint32_t k2 = k0 ^ k1 ^ 0x1BD11BDAu;
        m8 = mask8(k0, k1, k2, (uint32_t)(row * DIM + g * 8));
    }

    float m[8] = {0.f, 0.f, 0.f, 0.f, 0.f, 0.f, 0.f, 0.f};
    int j = s;
    for (; j + 3 < e; j += 4) {
        int2 e0 = __ldcs(edges + j),     e1 = __ldcs(edges + j + 1);
        int2 e2 = __ldcs(edges + j + 2), e3 = __ldcs(edges + j + 3);
        uint4 a0 = __ldg(X + (size_t)e0.x * D16 + g);
        uint4 a1 = __ldg(X + (size_t)e1.x * D16 + g);
        uint4 a2 = __ldg(X + (size_t)e2.x * D16 + g);
        uint4 a3 = __ldg(X + (size_t)e3.x * D16 + g);
        acc8(m, __int_as_float(e0.y), a0);
        acc8(m, __int_as_float(e1.y), a1);
        acc8(m, __int_as_float(e2.y), a2);
        acc8(m, __int_as_float(e3.y), a3);
    }
    for (; j < e; j++) {
        int2 e0 = __ldcs(edges + j);
        uint4 a0 = __ldg(X + (size_t)e0.x * D16 + g);
        acc8(m, __int_as_float(e0.y), a0);
    }

    size_t i4 = (size_t)row * D4 + g * 2;      // two float4 per lane (fp32 bufs)
    float pv[8];
    if (mode == 0) {
        float4 p0 = poi[i4], p1 = poi[i4 + 1];
        pv[0] = p0.x; pv[1] = p0.y; pv[2] = p0.z; pv[3] = p0.w;
        pv[4] = p1.x; pv[5] = p1.y; pv[6] = p1.z; pv[7] = p1.w;
    } else {
        unpack8(pv, xprev16[(size_t)row * D16 + g]);
    }

    float v[8];
    #pragma unroll
    for (int t = 0; t < 8; t++)
        v[t] = ((m8 >> t) & 1u) ? (m[t] + pv[t]) * KEEP_INV : 0.0f;

    if (mode == 0) {
        xout16[(size_t)row * D16 + g] = pack8(v);
        accbuf[i4]     = make_float4(pv[0] + v[0], pv[1] + v[1], pv[2] + v[2], pv[3] + v[3]);
        accbuf[i4 + 1] = make_float4(pv[4] + v[4], pv[5] + v[5], pv[6] + v[6], pv[7] + v[7]);
    } else if (mode == 1) {
        xout16[(size_t)row * D16 + g] = pack8(v);
        float4 a0 = accbuf[i4], a1 = accbuf[i4 + 1];
        accbuf[i4]     = make_float4(a0.x + v[0], a0.y + v[1], a0.z + v[2], a0.w + v[3]);
        accbuf[i4 + 1] = make_float4(a1.x + v[4], a1.y + v[5], a1.z + v[6], a1.w + v[7]);
    } else {
        float4 a0 = accbuf[i4], a1 = accbuf[i4 + 1];
        out[i4]     = make_float4((a0.x + v[0]) * 0.25f, (a0.y + v[1]) * 0.25f,
                                  (a0.z + v[2]) * 0.25f, (a0.w + v[3]) * 0.25f);
        out[i4 + 1] = make_float4((a1.x + v[4]) * 0.25f, (a1.y + v[5]) * 0.25f,
                                  (a1.z + v[6]) * 0.25f, (a1.w + v[7]) * 0.25f);
    }
}

// ---------------- host-side threefry (per-layer fold_in keys) ---------------
static inline unsigned h_rotl(unsigned x, int r) { return (x << r) | (x >> (32 - r)); }
static void host_threefry(unsigned k0, unsigned k1, unsigned x0, unsigned x1,
                          unsigned* o0, unsigned* o1)
{
    const int rots[2][4] = {{13, 15, 26, 6}, {17, 29, 16, 24}};
    unsigned ks[3] = {k0, k1, k0 ^ k1 ^ 0x1BD11BDAu};
    x0 += ks[0]; x1 += ks[1];
    for (int g = 0; g < 5; g++) {
        for (int j = 0; j < 4; j++) {
            x0 += x1; x1 = h_rotl(x1, rots[g & 1][j]); x1 ^= x0;
        }
        x0 += ks[(g + 1) % 3];
        x1 += ks[(g + 2) % 3] + (unsigned)(g + 1);
    }
    *o0 = x0; *o1 = x1;
}

extern "C" void kernel_launch(void* const* d_in, const int* in_sizes, int n_in,
                              void* d_out, int out_size)
{
    const float* poi     = (const float*)d_in[0];
    const int*   src_row = (const int*)  d_in[1];
    const int*   src_col = (const int*)  d_in[2];
    const float* src_val = (const float*)d_in[3];
    const int*   tar_row = (const int*)  d_in[4];
    const int*   tar_col = (const int*)  d_in[5];
    const float* tar_val = (const float*)d_in[6];
    int nnz = in_sizes[1];

    float4 *acc;
    uint4 *x16, *mt16;
    uint8_t *mask;
    int *rp_s, *rp_t, *cnt, *rank_t, *rank_s;
    int2 *es, *et;
    cudaGetSymbolAddress((void**)&acc,    g_acc);
    cudaGetSymbolAddress((void**)&x16,    g_x16);
    cudaGetSymbolAddress((void**)&mt16,   g_mt16);
    cudaGetSymbolAddress((void**)&mask,   g_mask);
    cudaGetSymbolAddress((void**)&rp_s,   g_rp_src);
    cudaGetSymbolAddress((void**)&rp_t,   g_rp_tar);
    cudaGetSymbolAddress((void**)&cnt,    g_cnt);
    cudaGetSymbolAddress((void**)&rank_t, g_rank_t);
    cudaGetSymbolAddress((void**)&rank_s, g_rank_s);
    cudaGetSymbolAddress((void**)&es,     g_e_src);
    cudaGetSymbolAddress((void**)&et,     g_e_tar);

    unsigned lk0[3], lk1[3];
    for (unsigned i = 0; i < 3; i++)
        host_threefry(0u, 42u, 0u, i, &lk0[i], &lk1[i]);

    int eb = (nnz + 255) / 256;
    int rb = NPOI / 8;
    int cb = (NPOI * D16 + 255) / 256;

    // ---- fused CSR build + fp16 snapshot + mask rows [0,M2) x 3 layers -----
    cudaMemsetAsync(cnt, 0, 2 * NPOI * sizeof(int), 0);
    cvt16_kernel<<<cb, 256>>>((const float4*)poi, x16);
    hist2_kernel<<<eb, 256>>>(tar_row, src_row, cnt, rank_t, rank_s, mask, nnz,
                              lk0[0], lk1[0], lk0[1], lk1[1], lk0[2], lk1[2]);
    scan2_kernel<<<2, 1024>>>(cnt, rp_t, rp_s);
    scatter2_kernel<<<eb, 256>>>(tar_row, tar_col, tar_val,
                                 src_row, src_col, src_val,
                                 rp_t, rp_s, rank_t, rank_s, et, es, mask, nnz,
                                 lk0[0], lk1[0], lk0[1], lk1[1], lk0[2], lk1[2]);

    // ---- 3 layers ----
    for (int i = 0; i < 3; i++) {
        uint8_t* maskL = mask + (size_t)i * MASKB;
        spmm_h<<<rb, 256>>>(rp_t, et, x16, mt16, maskL, lk0[i], lk1[i]);
        spmm_h_fused<<<rb, 256>>>(rp_s, es, mt16, maskL,
                                  (const float4*)poi, x16,
                                  x16, acc, (float4*)d_out,
                                  lk0[i], lk1[i], i);
    }
}